// round 10
// baseline (speedup 1.0000x reference)
#include <cuda_runtime.h>
#include <cuda_fp16.h>
#include <cstdint>

// ============================================================================
// out[M,N] = X[M,K] @ sign(W)[N,K]^T + bias[N],  M=N=K=4096, fp32.
// sm_103 plain PTX target => legacy mma.sync fp16 path.
// History: dual bf16 711us (R3); s8 IMMA banned (R4); fp16 412us (R6);
// 2 CTA/SM 356us (R7); 4-warp 64x64 340us (R8); BN=64 3 CTA/SM 359us -
// REGRESSED, L2 traffic up 50% (R9).
// R10: R8 config (128x128, 4 warps, 2 CTA/SM) + single barrier per chunk.
// ============================================================================

static constexpr int MM = 4096;
static constexpr int NN = 4096;
static constexpr int KK = 4096;

static constexpr int BM = 128;
static constexpr int BN = 128;
static constexpr int BK = 64;            // 64 fp16 = 128B row
static constexpr int STAGES = 3;
static constexpr int CHUNKS = KK / BK;   // 64
static constexpr int THREADS = 128;      // 4 warps: 2 (M) x 2 (N), warp 64x64

// SMEM stage layout (bytes)
static constexpr int A_BYTES = BM * 128;           // 16384
static constexpr int B_BYTES = BN * 128;           // 16384
static constexpr int A_OFF = 0;
static constexpr int B_OFF = A_BYTES;
static constexpr int STAGE_BYTES = A_BYTES + B_BYTES;   // 32768
static constexpr int SMEM_TOTAL = STAGES * STAGE_BYTES; // 98304

// ---------------------------------------------------------------------------
// Scratch (allocation-free)
// ---------------------------------------------------------------------------
__device__ __align__(1024) __half g_xa[(size_t)MM * KK];
__device__ __align__(1024) __half g_wb[(size_t)NN * KK];

// ---------------------------------------------------------------------------
// helpers
// ---------------------------------------------------------------------------
__device__ __forceinline__ uint32_t smem_u32(const void* p) {
    uint32_t a;
    asm("{ .reg .u64 t; cvta.to.shared.u64 t, %1; cvt.u32.u64 %0, t; }"
        : "=r"(a) : "l"(p));
    return a;
}

#define CP_ASYNC_16(dst, src) \
    asm volatile("cp.async.cg.shared.global [%0], [%1], 16;" \
        :: "r"(dst), "l"(src) : "memory")
#define CP_ASYNC_COMMIT() asm volatile("cp.async.commit_group;" ::: "memory")
#define CP_ASYNC_WAIT_1() asm volatile("cp.async.wait_group 1;" ::: "memory")

__device__ __forceinline__ void ldmatrix_x4(uint32_t& r0, uint32_t& r1,
                                            uint32_t& r2, uint32_t& r3,
                                            uint32_t addr) {
    asm volatile("ldmatrix.sync.aligned.m8n8.x4.shared.b16 {%0,%1,%2,%3}, [%4];"
                 : "=r"(r0), "=r"(r1), "=r"(r2), "=r"(r3) : "r"(addr));
}

__device__ __forceinline__ void mma_f16(float* d, const uint32_t* a,
                                        uint32_t b0, uint32_t b1) {
    asm volatile(
        "mma.sync.aligned.m16n8k16.row.col.f32.f16.f16.f32 "
        "{%0,%1,%2,%3}, {%4,%5,%6,%7}, {%8,%9}, {%0,%1,%2,%3};"
        : "+f"(d[0]), "+f"(d[1]), "+f"(d[2]), "+f"(d[3])
        : "r"(a[0]), "r"(a[1]), "r"(a[2]), "r"(a[3]), "r"(b0), "r"(b1));
}

// ---------------------------------------------------------------------------
// Conversion kernels
// ---------------------------------------------------------------------------
__global__ void __launch_bounds__(256) convert_x_kernel(
    const float4* __restrict__ x, uint2* __restrict__ xa) {
    int i = blockIdx.x * 256 + threadIdx.x;
    float4 v = x[i];
    __half2 p01 = __floats2half2_rn(v.x, v.y);
    __half2 p23 = __floats2half2_rn(v.z, v.w);
    uint2 p;
    p.x = *reinterpret_cast<uint32_t*>(&p01);
    p.y = *reinterpret_cast<uint32_t*>(&p23);
    xa[i] = p;
}

__global__ void __launch_bounds__(256) convert_w_kernel(
    const float4* __restrict__ w, uint2* __restrict__ wb) {
    int i = blockIdx.x * 256 + threadIdx.x;
    float4 v = w[i];
    float s0 = (v.x > 0.f) ? 1.f : ((v.x < 0.f) ? -1.f : 0.f);
    float s1 = (v.y > 0.f) ? 1.f : ((v.y < 0.f) ? -1.f : 0.f);
    float s2 = (v.z > 0.f) ? 1.f : ((v.z < 0.f) ? -1.f : 0.f);
    float s3 = (v.w > 0.f) ? 1.f : ((v.w < 0.f) ? -1.f : 0.f);
    __half2 p01 = __floats2half2_rn(s0, s1);
    __half2 p23 = __floats2half2_rn(s2, s3);
    uint2 p;
    p.x = *reinterpret_cast<uint32_t*>(&p01);
    p.y = *reinterpret_cast<uint32_t*>(&p23);
    wb[i] = p;
}

// ---------------------------------------------------------------------------
// GEMM kernel (single fp16 pass, 4 warps, 2 CTAs/SM)
// ---------------------------------------------------------------------------
__global__ void __launch_bounds__(THREADS, 2)
bingemm_kernel(const __half* __restrict__ xa,
               const __half* __restrict__ wb,
               const float* __restrict__ bias,
               float* __restrict__ out) {
    extern __shared__ __align__(1024) char smem[];
    const uint32_t sb = smem_u32(smem);

    const int tid = threadIdx.x;
    const int wid = tid >> 5;
    const int lane = tid & 31;
    const int warp_m = wid & 1;    // 0..1 -> 64 rows
    const int warp_n = wid >> 1;   // 0..1 -> 64 cols
    const int m0 = blockIdx.y * BM;
    const int n0 = blockIdx.x * BN;

    // --- cp.async tile loader (row = 128B = 8 x 16B chunks, xor swizzle) ---
    const int ld_row = tid >> 3;   // 0..15
    const int ld_chunk = tid & 7;  // 0..7

    auto load_stage = [&](int stage, int c) {
        const uint32_t sbase = sb + stage * STAGE_BYTES;
        const int k0 = c * BK;
        #pragma unroll
        for (int i = 0; i < 8; i++) {
            int row = i * 16 + ld_row;
            uint32_t soff = row * 128 + ((ld_chunk ^ (row & 7)) << 4);
            CP_ASYNC_16(sbase + A_OFF + soff,
                        xa + (size_t)(m0 + row) * KK + k0 + ld_chunk * 8);
        }
        #pragma unroll
        for (int i = 0; i < 8; i++) {
            int row = i * 16 + ld_row;
            uint32_t soff = row * 128 + ((ld_chunk ^ (row & 7)) << 4);
            CP_ASYNC_16(sbase + B_OFF + soff,
                        wb + (size_t)(n0 + row) * KK + k0 + ld_chunk * 8);
        }
    };

    // prologue: 2 stages in flight
    load_stage(0, 0); CP_ASYNC_COMMIT();
    load_stage(1, 1); CP_ASYNC_COMMIT();

    // --- ldmatrix per-thread address components ---
    const int mt = lane >> 3;            // matrix index 0..3
    const int lrow = lane & 7;
    // A mats: (m+0,kc0) (m+8,kc0) (m+0,kc1) (m+8,kc1)
    const int a_row = warp_m * 64 + lrow + ((mt & 1) << 3);   // + mi*16
    const int a_koff = mt >> 1;
    // B mats: (n+0,kc0) (n+0,kc1) (n+8,kc0) (n+8,kc1)
    const int b_row = warp_n * 64 + lrow + ((mt >> 1) << 3);  // + nj2*16
    const int b_koff = mt & 1;

    float acc[4][8][4];                  // mi, nj (8 x n8), quad
    #pragma unroll
    for (int mi = 0; mi < 4; mi++)
        #pragma unroll
        for (int nj = 0; nj < 8; nj++)
            #pragma unroll
            for (int q = 0; q < 4; q++) acc[mi][nj][q] = 0.f;

    for (int c = 0; c < CHUNKS; c++) {
        // Single barrier per chunk: the wait+sync here also proves every warp
        // finished chunk c-1, so overwriting stage (c+2)%3 below is safe.
        CP_ASYNC_WAIT_1();
        __syncthreads();
        if (c + 2 < CHUNKS) load_stage((c + 2) % STAGES, c + 2);
        CP_ASYNC_COMMIT();

        const uint32_t sbase = sb + (c % STAGES) * STAGE_BYTES;

        #pragma unroll
        for (int ks = 0; ks < 4; ks++) {
            // B fragments: 4 x ldmatrix.x4 -> 8 n8 slices
            uint32_t b[4][4];
            #pragma unroll
            for (int nj2 = 0; nj2 < 4; nj2++) {
                int row = b_row + nj2 * 16;
                int kch = ks * 2 + b_koff;
                uint32_t off = row * 128 + ((kch ^ (row & 7)) << 4);
                ldmatrix_x4(b[nj2][0], b[nj2][1], b[nj2][2], b[nj2][3],
                            sbase + B_OFF + off);
            }
            // A fragments just-in-time per 16-row slice
            #pragma unroll
            for (int mi = 0; mi < 4; mi++) {
                int row = a_row + mi * 16;
                int kch = ks * 2 + a_koff;
                uint32_t off = row * 128 + ((kch ^ (row & 7)) << 4);
                uint32_t a[4];
                ldmatrix_x4(a[0], a[1], a[2], a[3], sbase + A_OFF + off);
                #pragma unroll
                for (int nj2 = 0; nj2 < 4; nj2++) {
                    mma_f16(acc[mi][nj2 * 2 + 0], a, b[nj2][0], b[nj2][1]);
                    mma_f16(acc[mi][nj2 * 2 + 1], a, b[nj2][2], b[nj2][3]);
                }
            }
        }
    }

    // --- epilogue: += bias, write fp32 ---
    const int qcol = (lane & 3) * 2;
    float2 bv[8];
    #pragma unroll
    for (int nj = 0; nj < 8; nj++)
        bv[nj] = *reinterpret_cast<const float2*>(
            bias + n0 + warp_n * 64 + nj * 8 + qcol);

    #pragma unroll
    for (int mi = 0; mi < 4; mi++) {
        int r0 = m0 + warp_m * 64 + mi * 16 + (lane >> 2);
        float* p0 = out + (size_t)r0 * NN + n0 + warp_n * 64 + qcol;
        float* p1 = p0 + 8 * NN;
        #pragma unroll
        for (int nj = 0; nj < 8; nj++) {
            float2 v0, v1;
            v0.x = acc[mi][nj][0] + bv[nj].x;
            v0.y = acc[mi][nj][1] + bv[nj].y;
            v1.x = acc[mi][nj][2] + bv[nj].x;
            v1.y = acc[mi][nj][3] + bv[nj].y;
            *reinterpret_cast<float2*>(p0 + nj * 8) = v0;
            *reinterpret_cast<float2*>(p1 + nj * 8) = v1;
        }
    }
}

// ---------------------------------------------------------------------------
// Host launch
// ---------------------------------------------------------------------------
extern "C" void kernel_launch(void* const* d_in, const int* in_sizes, int n_in,
                              void* d_out, int out_size) {
    const float* x    = (const float*)d_in[0];
    const float* w    = (const float*)d_in[1];
    const float* bias = (const float*)d_in[2];
    float* out = (float*)d_out;

    void *p_xa = nullptr, *p_wb = nullptr;
    cudaGetSymbolAddress(&p_xa, g_xa);
    cudaGetSymbolAddress(&p_wb, g_wb);

    const int n4 = MM * KK / 4;
    convert_x_kernel<<<n4 / 256, 256>>>((const float4*)x, (uint2*)p_xa);
    convert_w_kernel<<<n4 / 256, 256>>>((const float4*)w, (uint2*)p_wb);

    static bool attr_set = false;
    if (!attr_set) {
        cudaFuncSetAttribute(bingemm_kernel,
                             cudaFuncAttributeMaxDynamicSharedMemorySize, SMEM_TOTAL);
        attr_set = true;
    }

    dim3 grid(NN / BN, MM / BM);  // (32, 32) = 1024 CTAs
    bingemm_kernel<<<grid, THREADS, SMEM_TOTAL>>>(
        (const __half*)p_xa, (const __half*)p_wb, bias, out);
}

// round 11
// speedup vs baseline: 1.0224x; 1.0224x over previous
#include <cuda_runtime.h>
#include <cuda_fp16.h>
#include <cstdint>

// ============================================================================
// out[M,N] = X[M,K] @ sign(W)[N,K]^T + bias[N],  M=N=K=4096, fp32.
// sm_103 plain PTX target => legacy mma.sync fp16 path.
// History: dual bf16 711us (R3); s8 IMMA banned (R4); fp16 412us (R6);
// 2 CTA/SM 356us (R7); 4-warp 64x64 + 2 barriers/chunk 340us (R8);
// BN=64 3CTA/SM 359us REGRESSED (R9); single barrier 363us REGRESSED (R10).
// R11: R8 config exactly (incl. both barriers) + software-pipelined
// fragment loads: B double-buffered across ks, A double-buffered across mi.
// ============================================================================

static constexpr int MM = 4096;
static constexpr int NN = 4096;
static constexpr int KK = 4096;

static constexpr int BM = 128;
static constexpr int BN = 128;
static constexpr int BK = 64;            // 64 fp16 = 128B row
static constexpr int STAGES = 3;
static constexpr int CHUNKS = KK / BK;   // 64
static constexpr int THREADS = 128;      // 4 warps: 2 (M) x 2 (N), warp 64x64

// SMEM stage layout (bytes)
static constexpr int A_BYTES = BM * 128;           // 16384
static constexpr int B_BYTES = BN * 128;           // 16384
static constexpr int A_OFF = 0;
static constexpr int B_OFF = A_BYTES;
static constexpr int STAGE_BYTES = A_BYTES + B_BYTES;   // 32768
static constexpr int SMEM_TOTAL = STAGES * STAGE_BYTES; // 98304

// ---------------------------------------------------------------------------
// Scratch (allocation-free)
// ---------------------------------------------------------------------------
__device__ __align__(1024) __half g_xa[(size_t)MM * KK];
__device__ __align__(1024) __half g_wb[(size_t)NN * KK];

// ---------------------------------------------------------------------------
// helpers
// ---------------------------------------------------------------------------
__device__ __forceinline__ uint32_t smem_u32(const void* p) {
    uint32_t a;
    asm("{ .reg .u64 t; cvta.to.shared.u64 t, %1; cvt.u32.u64 %0, t; }"
        : "=r"(a) : "l"(p));
    return a;
}

#define CP_ASYNC_16(dst, src) \
    asm volatile("cp.async.cg.shared.global [%0], [%1], 16;" \
        :: "r"(dst), "l"(src) : "memory")
#define CP_ASYNC_COMMIT() asm volatile("cp.async.commit_group;" ::: "memory")
#define CP_ASYNC_WAIT_1() asm volatile("cp.async.wait_group 1;" ::: "memory")

__device__ __forceinline__ void ldmatrix_x4(uint32_t& r0, uint32_t& r1,
                                            uint32_t& r2, uint32_t& r3,
                                            uint32_t addr) {
    asm volatile("ldmatrix.sync.aligned.m8n8.x4.shared.b16 {%0,%1,%2,%3}, [%4];"
                 : "=r"(r0), "=r"(r1), "=r"(r2), "=r"(r3) : "r"(addr));
}

__device__ __forceinline__ void mma_f16(float* d, const uint32_t* a,
                                        uint32_t b0, uint32_t b1) {
    asm volatile(
        "mma.sync.aligned.m16n8k16.row.col.f32.f16.f16.f32 "
        "{%0,%1,%2,%3}, {%4,%5,%6,%7}, {%8,%9}, {%0,%1,%2,%3};"
        : "+f"(d[0]), "+f"(d[1]), "+f"(d[2]), "+f"(d[3])
        : "r"(a[0]), "r"(a[1]), "r"(a[2]), "r"(a[3]), "r"(b0), "r"(b1));
}

// ---------------------------------------------------------------------------
// Conversion kernels
// ---------------------------------------------------------------------------
__global__ void __launch_bounds__(256) convert_x_kernel(
    const float4* __restrict__ x, uint2* __restrict__ xa) {
    int i = blockIdx.x * 256 + threadIdx.x;
    float4 v = x[i];
    __half2 p01 = __floats2half2_rn(v.x, v.y);
    __half2 p23 = __floats2half2_rn(v.z, v.w);
    uint2 p;
    p.x = *reinterpret_cast<uint32_t*>(&p01);
    p.y = *reinterpret_cast<uint32_t*>(&p23);
    xa[i] = p;
}

__global__ void __launch_bounds__(256) convert_w_kernel(
    const float4* __restrict__ w, uint2* __restrict__ wb) {
    int i = blockIdx.x * 256 + threadIdx.x;
    float4 v = w[i];
    float s0 = (v.x > 0.f) ? 1.f : ((v.x < 0.f) ? -1.f : 0.f);
    float s1 = (v.y > 0.f) ? 1.f : ((v.y < 0.f) ? -1.f : 0.f);
    float s2 = (v.z > 0.f) ? 1.f : ((v.z < 0.f) ? -1.f : 0.f);
    float s3 = (v.w > 0.f) ? 1.f : ((v.w < 0.f) ? -1.f : 0.f);
    __half2 p01 = __floats2half2_rn(s0, s1);
    __half2 p23 = __floats2half2_rn(s2, s3);
    uint2 p;
    p.x = *reinterpret_cast<uint32_t*>(&p01);
    p.y = *reinterpret_cast<uint32_t*>(&p23);
    wb[i] = p;
}

// ---------------------------------------------------------------------------
// GEMM kernel (single fp16 pass, 4 warps, 2 CTAs/SM)
// ---------------------------------------------------------------------------
__global__ void __launch_bounds__(THREADS, 2)
bingemm_kernel(const __half* __restrict__ xa,
               const __half* __restrict__ wb,
               const float* __restrict__ bias,
               float* __restrict__ out) {
    extern __shared__ __align__(1024) char smem[];
    const uint32_t sb = smem_u32(smem);

    const int tid = threadIdx.x;
    const int wid = tid >> 5;
    const int lane = tid & 31;
    const int warp_m = wid & 1;    // 0..1 -> 64 rows
    const int warp_n = wid >> 1;   // 0..1 -> 64 cols
    const int m0 = blockIdx.y * BM;
    const int n0 = blockIdx.x * BN;

    // --- cp.async tile loader (row = 128B = 8 x 16B chunks, xor swizzle) ---
    const int ld_row = tid >> 3;   // 0..15
    const int ld_chunk = tid & 7;  // 0..7

    auto load_stage = [&](int stage, int c) {
        const uint32_t sbase = sb + stage * STAGE_BYTES;
        const int k0 = c * BK;
        #pragma unroll
        for (int i = 0; i < 8; i++) {
            int row = i * 16 + ld_row;
            uint32_t soff = row * 128 + ((ld_chunk ^ (row & 7)) << 4);
            CP_ASYNC_16(sbase + A_OFF + soff,
                        xa + (size_t)(m0 + row) * KK + k0 + ld_chunk * 8);
        }
        #pragma unroll
        for (int i = 0; i < 8; i++) {
            int row = i * 16 + ld_row;
            uint32_t soff = row * 128 + ((ld_chunk ^ (row & 7)) << 4);
            CP_ASYNC_16(sbase + B_OFF + soff,
                        wb + (size_t)(n0 + row) * KK + k0 + ld_chunk * 8);
        }
    };

    // prologue: 2 stages in flight
    load_stage(0, 0); CP_ASYNC_COMMIT();
    load_stage(1, 1); CP_ASYNC_COMMIT();

    // --- ldmatrix per-thread address components ---
    const int mt = lane >> 3;            // matrix index 0..3
    const int lrow = lane & 7;
    // A mats: (m+0,kc0) (m+8,kc0) (m+0,kc1) (m+8,kc1)
    const int a_row = warp_m * 64 + lrow + ((mt & 1) << 3);   // + mi*16
    const int a_koff = mt >> 1;
    // B mats: (n+0,kc0) (n+0,kc1) (n+8,kc0) (n+8,kc1)
    const int b_row = warp_n * 64 + lrow + ((mt >> 1) << 3);  // + nj2*16
    const int b_koff = mt & 1;

    float acc[4][8][4];                  // mi, nj (8 x n8), quad
    #pragma unroll
    for (int mi = 0; mi < 4; mi++)
        #pragma unroll
        for (int nj = 0; nj < 8; nj++)
            #pragma unroll
            for (int q = 0; q < 4; q++) acc[mi][nj][q] = 0.f;

    for (int c = 0; c < CHUNKS; c++) {
        CP_ASYNC_WAIT_1();
        __syncthreads();
        if (c + 2 < CHUNKS) load_stage((c + 2) % STAGES, c + 2);
        CP_ASYNC_COMMIT();

        const uint32_t sbase = sb + (c % STAGES) * STAGE_BYTES;

        auto a_addr = [&](int mi, int ks) -> uint32_t {
            int row = a_row + mi * 16;
            int kch = ks * 2 + a_koff;
            return sbase + A_OFF + row * 128 + ((kch ^ (row & 7)) << 4);
        };
        auto b_addr = [&](int nj2, int ks) -> uint32_t {
            int row = b_row + nj2 * 16;
            int kch = ks * 2 + b_koff;
            return sbase + B_OFF + row * 128 + ((kch ^ (row & 7)) << 4);
        };

        // Software-pipelined fragment loads:
        //   B double-buffered at ks granularity (load ks+1 before MMAs of ks)
        //   A double-buffered at mi granularity (load next before MMAs of cur)
        uint32_t bB[2][4][4];
        uint32_t bA[2][4];

        #pragma unroll
        for (int nj2 = 0; nj2 < 4; nj2++)
            ldmatrix_x4(bB[0][nj2][0], bB[0][nj2][1], bB[0][nj2][2],
                        bB[0][nj2][3], b_addr(nj2, 0));
        ldmatrix_x4(bA[0][0], bA[0][1], bA[0][2], bA[0][3], a_addr(0, 0));

        #pragma unroll
        for (int ks = 0; ks < 4; ks++) {
            if (ks < 3) {
                #pragma unroll
                for (int nj2 = 0; nj2 < 4; nj2++)
                    ldmatrix_x4(bB[(ks + 1) & 1][nj2][0], bB[(ks + 1) & 1][nj2][1],
                                bB[(ks + 1) & 1][nj2][2], bB[(ks + 1) & 1][nj2][3],
                                b_addr(nj2, ks + 1));
            }
            #pragma unroll
            for (int mi = 0; mi < 4; mi++) {
                const int cur = (ks * 4 + mi) & 1;
                const int nxt = cur ^ 1;
                // prefetch next A fragment (wraps to (0,0) at the very end;
                // harmless redundant load within the same resident stage)
                const int nmi = (mi + 1) & 3;
                const int nks = (mi == 3) ? ((ks + 1) & 3) : ks;
                ldmatrix_x4(bA[nxt][0], bA[nxt][1], bA[nxt][2], bA[nxt][3],
                            a_addr(nmi, nks));
                #pragma unroll
                for (int nj2 = 0; nj2 < 4; nj2++) {
                    mma_f16(acc[mi][nj2 * 2 + 0], bA[cur],
                            bB[ks & 1][nj2][0], bB[ks & 1][nj2][1]);
                    mma_f16(acc[mi][nj2 * 2 + 1], bA[cur],
                            bB[ks & 1][nj2][2], bB[ks & 1][nj2][3]);
                }
            }
        }
        __syncthreads();
    }

    // --- epilogue: += bias, write fp32 ---
    const int qcol = (lane & 3) * 2;
    float2 bv[8];
    #pragma unroll
    for (int nj = 0; nj < 8; nj++)
        bv[nj] = *reinterpret_cast<const float2*>(
            bias + n0 + warp_n * 64 + nj * 8 + qcol);

    #pragma unroll
    for (int mi = 0; mi < 4; mi++) {
        int r0 = m0 + warp_m * 64 + mi * 16 + (lane >> 2);
        float* p0 = out + (size_t)r0 * NN + n0 + warp_n * 64 + qcol;
        float* p1 = p0 + 8 * NN;
        #pragma unroll
        for (int nj = 0; nj < 8; nj++) {
            float2 v0, v1;
            v0.x = acc[mi][nj][0] + bv[nj].x;
            v0.y = acc[mi][nj][1] + bv[nj].y;
            v1.x = acc[mi][nj][2] + bv[nj].x;
            v1.y = acc[mi][nj][3] + bv[nj].y;
            *reinterpret_cast<float2*>(p0 + nj * 8) = v0;
            *reinterpret_cast<float2*>(p1 + nj * 8) = v1;
        }
    }
}

// ---------------------------------------------------------------------------
// Host launch
// ---------------------------------------------------------------------------
extern "C" void kernel_launch(void* const* d_in, const int* in_sizes, int n_in,
                              void* d_out, int out_size) {
    const float* x    = (const float*)d_in[0];
    const float* w    = (const float*)d_in[1];
    const float* bias = (const float*)d_in[2];
    float* out = (float*)d_out;

    void *p_xa = nullptr, *p_wb = nullptr;
    cudaGetSymbolAddress(&p_xa, g_xa);
    cudaGetSymbolAddress(&p_wb, g_wb);

    const int n4 = MM * KK / 4;
    convert_x_kernel<<<n4 / 256, 256>>>((const float4*)x, (uint2*)p_xa);
    convert_w_kernel<<<n4 / 256, 256>>>((const float4*)w, (uint2*)p_wb);

    static bool attr_set = false;
    if (!attr_set) {
        cudaFuncSetAttribute(bingemm_kernel,
                             cudaFuncAttributeMaxDynamicSharedMemorySize, SMEM_TOTAL);
        attr_set = true;
    }

    dim3 grid(NN / BN, MM / BM);  // (32, 32) = 1024 CTAs
    bingemm_kernel<<<grid, THREADS, SMEM_TOTAL>>>(
        (const __half*)p_xa, (const __half*)p_wb, bias, out);
}